// round 11
// baseline (speedup 1.0000x reference)
#include <cuda_runtime.h>
#include <cuda_fp16.h>
#include <cstdint>
#include <cstddef>

// ===================== problem constants =====================
constexpr int B_SZ = 8;
constexpr int N_SZ = 2048;
constexpr int D_SZ = 128;

// ===================== GEMM tiling: CTA 32(M) x 128(N) x 32(K) =============
constexpr int SAH = 40;                  // A16 stage row stride (halves)
constexpr int SBH = 40;                  // B stage row stride (halves)
constexpr int A32_B = 32 * 32 * 4;       // 4096 B per fp32 A stage
constexpr int A16_B = 32 * SAH * 2;      // 2560 B per fp16 A stage
constexpr int B_STG = 128 * SBH * 2;     // 10240 B per B stage
constexpr int A32_RING = 4 * A32_B;      // 16384
constexpr int A16_RING = 4 * A16_B;      // 10240
constexpr int B_RING = 4 * B_STG;        // 40960
constexpr int A16_OFF = A32_RING;        // 16384
constexpr int B_OFF = A32_RING + A16_RING; // 26624
constexpr int K_ITERS = N_SZ / 32;       // 64
constexpr unsigned DYN_B = A32_RING + A16_RING + B_RING + 256;  // 67840

// h kernel tiling (tf32 path)
constexpr int HS = 36;
constexpr int HSTG = 2 * 128 * HS;
constexpr unsigned DYN_H = 2 * HSTG * 4; // 73728 (also covers 128x136 half transpose buf)
constexpr int SHh = 136;                 // h transpose smem stride (halves)

// scratch: hT[b][e][j] = fp16(leaky_relu(x @ W^T))^T
__device__ __half g_hT[(size_t)B_SZ * D_SZ * N_SZ];

// ===================== helpers =====================
__device__ __forceinline__ uint32_t s2u(const void* p) {
    uint32_t a;
    asm("{ .reg .u64 t; cvta.to.shared.u64 t, %1; cvt.u32.u64 %0, t; }" : "=r"(a) : "l"(p));
    return a;
}
__device__ __forceinline__ void cp16(uint32_t dst, const void* src) {
    asm volatile("cp.async.cg.shared.global [%0], [%1], 16;" :: "r"(dst), "l"(src));
}
__device__ __forceinline__ uint32_t f2tf(float f) {
    uint32_t u;
    asm("cvt.rna.tf32.f32 %0, %1;" : "=r"(u) : "f"(f));
    return u;
}
__device__ __forceinline__ void mma_tf32(float* d, const uint32_t* a, const uint32_t* b) {
    asm volatile(
        "mma.sync.aligned.m16n8k8.row.col.f32.tf32.tf32.f32 "
        "{%0,%1,%2,%3}, {%4,%5,%6,%7}, {%8,%9}, {%0,%1,%2,%3};"
        : "+f"(d[0]), "+f"(d[1]), "+f"(d[2]), "+f"(d[3])
        : "r"(a[0]), "r"(a[1]), "r"(a[2]), "r"(a[3]), "r"(b[0]), "r"(b[1]));
}
__device__ __forceinline__ void mma_f16(float* d, const uint32_t* a,
                                        uint32_t b0, uint32_t b1) {
    asm volatile(
        "mma.sync.aligned.m16n8k16.row.col.f32.f16.f16.f32 "
        "{%0,%1,%2,%3}, {%4,%5,%6,%7}, {%8,%9}, {%0,%1,%2,%3};"
        : "+f"(d[0]), "+f"(d[1]), "+f"(d[2]), "+f"(d[3])
        : "r"(a[0]), "r"(a[1]), "r"(a[2]), "r"(a[3]), "r"(b0), "r"(b1));
}
#define LDSM4(r, addr)                                                          \
    asm volatile("ldmatrix.sync.aligned.m8n8.x4.shared.b16 {%0,%1,%2,%3}, [%4];" \
        : "=r"((r)[0]), "=r"((r)[1]), "=r"((r)[2]), "=r"((r)[3]) : "r"(addr))
__device__ __forceinline__ __half lrelu_h(float x) {
    float v = x > 0.f ? x : 0.01f * x;
    return __float2half_rn(v);
}

// ===================== kernel 1: hT = fp16(leaky_relu(x @ W^T))^T ===========
__global__ __launch_bounds__(256) void h_kernel(const float* __restrict__ x,
                                                const float* __restrict__ W) {
    extern __shared__ float hdyn[];
    const int tid = threadIdx.x;
    const int b = blockIdx.x >> 4;
    const int j0 = (blockIdx.x & 15) * 128;

    const int wid = tid >> 5;
    const int lane = tid & 31;
    const int g = lane >> 2;
    const int t4 = lane & 3;
    const int wm = wid & 3;
    const int wn = wid >> 2;

    const uint32_t smem_u = s2u(hdyn);
    const float* xg = x + ((size_t)b * N_SZ + j0) * D_SZ;

    auto load_stage = [&](int stage, int kt) {
        const uint32_t xbase = smem_u + stage * HSTG * 4;
        const uint32_t wbase = xbase + 128 * HS * 4;
#pragma unroll
        for (int i = 0; i < 4; i++) {
            int c = tid + i * 256;
            int r = c >> 3, d4 = (c & 7) * 4;
            cp16(xbase + (r * HS + d4) * 4, xg + (size_t)r * D_SZ + kt * 32 + d4);
            cp16(wbase + (r * HS + d4) * 4, W + (size_t)r * D_SZ + kt * 32 + d4);
        }
    };

    float acc[2][8][4];
#pragma unroll
    for (int mt = 0; mt < 2; mt++)
#pragma unroll
        for (int nt = 0; nt < 8; nt++)
#pragma unroll
            for (int q = 0; q < 4; q++) acc[mt][nt][q] = 0.f;

    load_stage(0, 0);
    asm volatile("cp.async.commit_group;" ::: "memory");

    for (int kt = 0; kt < 4; kt++) {
        asm volatile("cp.async.wait_group 0;" ::: "memory");
        __syncthreads();
        if (kt + 1 < 4) {
            load_stage((kt + 1) & 1, kt + 1);
            asm volatile("cp.async.commit_group;" ::: "memory");
        }
        const float* xs = hdyn + (kt & 1) * HSTG;
        const float* ws = xs + 128 * HS;

#pragma unroll
        for (int ks = 0; ks < 4; ks++) {
            uint32_t af[2][4], bf[8][2];
#pragma unroll
            for (int mt = 0; mt < 2; mt++) {
                int r0 = wm * 32 + mt * 16 + g;
                af[mt][0] = f2tf(xs[r0 * HS + ks * 8 + t4]);
                af[mt][1] = f2tf(xs[(r0 + 8) * HS + ks * 8 + t4]);
                af[mt][2] = f2tf(xs[r0 * HS + ks * 8 + t4 + 4]);
                af[mt][3] = f2tf(xs[(r0 + 8) * HS + ks * 8 + t4 + 4]);
            }
#pragma unroll
            for (int nt = 0; nt < 8; nt++) {
                int c0 = wn * 64 + nt * 8 + g;
                bf[nt][0] = f2tf(ws[c0 * HS + ks * 8 + t4]);
                bf[nt][1] = f2tf(ws[c0 * HS + ks * 8 + t4 + 4]);
            }
#pragma unroll
            for (int mt = 0; mt < 2; mt++)
#pragma unroll
                for (int nt = 0; nt < 8; nt++)
                    mma_tf32(acc[mt][nt], af[mt], bf[nt]);
        }
        __syncthreads();
    }

    // ---- transpose through smem, store fp16 hT[e][j] coalesced ----
    __half* hsm = reinterpret_cast<__half*>(hdyn);
#pragma unroll
    for (int mt = 0; mt < 2; mt++)
#pragma unroll
        for (int nt = 0; nt < 8; nt++) {
            int r = wm * 32 + mt * 16 + g;
            int c = wn * 64 + nt * 8 + t4 * 2;
            hsm[c * SHh + r]           = lrelu_h(acc[mt][nt][0]);
            hsm[(c + 1) * SHh + r]     = lrelu_h(acc[mt][nt][1]);
            hsm[c * SHh + r + 8]       = lrelu_h(acc[mt][nt][2]);
            hsm[(c + 1) * SHh + r + 8] = lrelu_h(acc[mt][nt][3]);
        }
    __syncthreads();

    const int e = tid >> 1;
    const int jh = (tid & 1) * 64;
    uint4* dst = reinterpret_cast<uint4*>(g_hT + ((size_t)b * D_SZ + e) * N_SZ + j0 + jh);
    const uint4* src = reinterpret_cast<const uint4*>(hsm + e * SHh + jh);
#pragma unroll
    for (int q = 0; q < 8; q++) dst[q] = src[q];
}

// ===================== kernel 2: fused normalize + An @ h (fp16 MMA) ========
// out[b,i,e] = ( sum_j A[b,i,j] h[b,j,e] + (1 - A[b,i,i]) h[b,i,e] ) / d_i
// d_i = rowsum(A[b,i,:]) - A[b,i,i] + 1
// CTA 32x128, 8 warps of 16x32, ldmatrix fragments, 3 CTAs/SM
__global__ __launch_bounds__(256, 3) void gcn_gemm_kernel(const float* __restrict__ A,
                                                          const __half* __restrict__ hTg,
                                                          float* __restrict__ out) {
    extern __shared__ float dyn[];
    __shared__ float rs_sm[256];
    __shared__ float corr_sm[32];
    __shared__ float dinv_sm[32];

    const int tid = threadIdx.x;
    const int b = blockIdx.x >> 6;
    const int gi0 = (blockIdx.x & 63) * 32;

    const int wid = tid >> 5;
    const int lane = tid & 31;
    const int g = lane >> 2;
    const int tg = lane & 3;
    const int wm = wid & 1;      // 2 row slices of 16
    const int wn = wid >> 1;     // 4 col slices of 32

    const float* Ag = A + (size_t)b * N_SZ * N_SZ;
    const __half* hTb = hTg + (size_t)b * D_SZ * N_SZ;

    // align dynamic smem base to 128B
    const uint32_t raw = s2u(dyn);
    const uint32_t base_u = (raw + 127u) & ~127u;
    char* dbase = reinterpret_cast<char*>(dyn) + (base_u - raw);

    const int r_lo = tid >> 3;           // 0..31
    const int kc = (tid & 7) * 4;        // k offset within 32
    float rs0 = 0.f;

    // ldmatrix per-lane base addresses (bytes)
    // A fragment (16x16): lanes 0-15 -> rows R0+l, k base 0; lanes 16-31 -> rows, k base +16B
    const uint32_t aoff = (uint32_t)((wm * 16 + (lane & 15)) * 80 + ((lane >> 4) * 16));
    // B fragment pair p (16 cols): lanes grouped per 8 into (cols, k0-7)/(cols, k8-15)
    const uint32_t boff0 = (uint32_t)((wn * 32 + (lane & 7) + ((lane >> 4) * 8)) * 80 +
                                      (((lane >> 3) & 1) * 16));
    const uint32_t boff1 = boff0 + 16 * 80;
    const uint32_t aAddrB = base_u + A16_OFF + aoff;
    const uint32_t bAddrB0 = base_u + B_OFF + boff0;
    const uint32_t bAddrB1 = base_u + B_OFF + boff1;

    // A fp32 tile t -> ring stage t&3 via cp.async (1 cp16/thread)
    auto cpA = [&](int t) {
        const uint32_t ab = base_u + (t & 3) * A32_B;
        cp16(ab + (r_lo * 32 + kc) * 4,
             Ag + (size_t)(gi0 + r_lo) * N_SZ + t * 32 + kc);
    };
    // B tile t -> ring stage t&3 via cp.async
    auto cpB = [&](int t) {
        const uint32_t bbase = base_u + B_OFF + (t & 3) * B_STG;
#pragma unroll
        for (int i = 0; i < 2; i++) {
            int c2 = tid + i * 256;
            int e = c2 >> 2, ch = c2 & 3;
            cp16(bbase + e * (SBH * 2) + ch * 16,
                 hTb + (size_t)e * N_SZ + t * 32 + ch * 8);
        }
    };
    // convert A32 tile t -> A16 stage t&3 (+ rowsum; each element counted once)
    auto convert = [&](int t) {
        const float* a32 = reinterpret_cast<const float*>(dbase + (t & 3) * A32_B);
        float4 v0 = *reinterpret_cast<const float4*>(a32 + r_lo * 32 + kc);
        __half2* ah = reinterpret_cast<__half2*>(dbase + A16_OFF + (t & 3) * A16_B);
        int i0 = r_lo * (SAH / 2) + (kc >> 1);
        ah[i0]     = __floats2half2_rn(v0.x, v0.y);
        ah[i0 + 1] = __floats2half2_rn(v0.z, v0.w);
        rs0 += (v0.x + v0.y) + (v0.z + v0.w);
    };

    float acc[4][4];
#pragma unroll
    for (int nt = 0; nt < 4; nt++)
#pragma unroll
        for (int q = 0; q < 4; q++) acc[nt][q] = 0.f;

    // ---- prologue (race-free; same schedule as R10) ----
    // g0{A0,A1,A2}, g1{B0,A3}, g2{B1}, [wait g0, convert 0,1], g3{B2,A4}
    cpA(0); cpA(1); cpA(2);
    asm volatile("cp.async.commit_group;" ::: "memory");   // g0
    cpB(0); cpA(3);
    asm volatile("cp.async.commit_group;" ::: "memory");   // g1
    cpB(1);
    asm volatile("cp.async.commit_group;" ::: "memory");   // g2
    asm volatile("cp.async.wait_group 2;" ::: "memory");   // g0 done
    __syncthreads();
    convert(0);
    convert(1);
    cpB(2); cpA(4);
    asm volatile("cp.async.commit_group;" ::: "memory");   // g3

    // steady state: wait guarantees g(kt+1) = {B(kt), A32(kt+2)}
#pragma unroll 2
    for (int kt = 0; kt < K_ITERS; kt++) {
        asm volatile("cp.async.wait_group 2;" ::: "memory");
        __syncthreads();

        if (kt + 3 < K_ITERS) cpB(kt + 3);
        if (kt + 5 < K_ITERS) cpA(kt + 5);
        asm volatile("cp.async.commit_group;" ::: "memory");

        if (kt + 2 < K_ITERS) convert(kt + 2);

        const uint32_t as = aAddrB + (kt & 3) * A16_B;
        const uint32_t bs0 = bAddrB0 + (kt & 3) * B_STG;
        const uint32_t bs1 = bAddrB1 + (kt & 3) * B_STG;

#pragma unroll
        for (int ks = 0; ks < 2; ks++) {
            uint32_t af[4], bf[4], cf[4];
            LDSM4(af, as + ks * 32);
            LDSM4(bf, bs0 + ks * 32);
            LDSM4(cf, bs1 + ks * 32);
            mma_f16(acc[0], af, bf[0], bf[1]);
            mma_f16(acc[1], af, bf[2], bf[3]);
            mma_f16(acc[2], af, cf[0], cf[1]);
            mma_f16(acc[3], af, cf[2], cf[3]);
        }
    }

    // ---- reductions & epilogue ----
    rs_sm[tid] = rs0;
    __syncthreads();                    // all compute done, rings dead

    if (tid < 32) {
        const float* srcp = rs_sm + tid * 8;
        float d = ((srcp[0] + srcp[1]) + (srcp[2] + srcp[3])) +
                  ((srcp[4] + srcp[5]) + (srcp[6] + srcp[7]));
        float aii = Ag[(size_t)(gi0 + tid) * (N_SZ + 1)];
        float c = 1.0f - aii;           // mask true: A>=0, rows strictly positive
        corr_sm[tid] = c;
        dinv_sm[tid] = 1.0f / (d + c);
    }

    float* o_sm = reinterpret_cast<float*>(dbase);            // [32][132] f32
    float* hf = reinterpret_cast<float*>(dbase) + 32 * 132;   // [128][33] f32
#pragma unroll
    for (int nt = 0; nt < 4; nt++) {
        int r = wm * 16 + g;
        int c = wn * 32 + nt * 8 + tg * 2;
        o_sm[r * 132 + c]           = acc[nt][0];
        o_sm[r * 132 + c + 1]       = acc[nt][1];
        o_sm[(r + 8) * 132 + c]     = acc[nt][2];
        o_sm[(r + 8) * 132 + c + 1] = acc[nt][3];
    }

    // load hT[:, gi0..gi0+32) tile -> float smem (for diag correction)
    {
        const int e = tid >> 1;
        const int part = tid & 1;
        const uint4* src = reinterpret_cast<const uint4*>(
            hTb + (size_t)e * N_SZ + gi0 + part * 16);
#pragma unroll
        for (int q = 0; q < 2; q++) {
            uint4 v = src[q];
            uint32_t w[4] = {v.x, v.y, v.z, v.w};
#pragma unroll
            for (int u = 0; u < 4; u++) {
                float2 f = __half22float2(*reinterpret_cast<__half2*>(&w[u]));
                hf[e * 33 + part * 16 + q * 8 + u * 2]     = f.x;
                hf[e * 33 + part * 16 + q * 8 + u * 2 + 1] = f.y;
            }
        }
    }
    __syncthreads();

    float* ob = out + ((size_t)b * N_SZ + gi0) * D_SZ;
#pragma unroll 4
    for (int i = tid; i < 32 * 128; i += 256) {
        int r = i >> 7, e = i & 127;
        ob[i] = (o_sm[r * 132 + e] + corr_sm[r] * hf[e * 33 + r]) * dinv_sm[r];
    }
}

// ===================== host =====================
extern "C" void kernel_launch(void* const* d_in, const int* in_sizes, int n_in,
                              void* d_out, int out_size) {
    const float* x = (const float*)d_in[0];
    const float* A = (const float*)d_in[1];
    const float* W = (const float*)d_in[2];
    float* out = (float*)d_out;

    void* hT_ptr = nullptr;
    cudaGetSymbolAddress(&hT_ptr, g_hT);

    cudaFuncSetAttribute(h_kernel, cudaFuncAttributeMaxDynamicSharedMemorySize, DYN_H);
    h_kernel<<<B_SZ * (N_SZ / 128), 256, DYN_H>>>(x, W);

    cudaFuncSetAttribute(gcn_gemm_kernel, cudaFuncAttributeMaxDynamicSharedMemorySize, DYN_B);
    gcn_gemm_kernel<<<B_SZ * (N_SZ / 32), 256, DYN_B>>>(A, (const __half*)hT_ptr, out);
    (void)in_sizes; (void)n_in; (void)out_size;
}

// round 12
// speedup vs baseline: 1.3041x; 1.3041x over previous
#include <cuda_runtime.h>
#include <cuda_fp16.h>
#include <cstdint>
#include <cstddef>

// ===================== problem constants =====================
constexpr int B_SZ = 8;
constexpr int N_SZ = 2048;
constexpr int D_SZ = 128;

// ===================== GEMM tiling: CTA 64(M) x 128(N) x 32(K) =============
constexpr int SAH = 40;                  // A16 stage row stride (halves) -> 80 B
constexpr int SBH = 40;                  // B stage row stride (halves)  -> 80 B
constexpr int A32_B = 64 * 32 * 4;       // 8192 B per fp32 A stage
constexpr int A16_B = 64 * SAH * 2;      // 5120 B per fp16 A stage
constexpr int B_STG = 128 * SBH * 2;     // 10240 B per B stage
constexpr int A32_RING = 4 * A32_B;      // 32768
constexpr int A16_RING = 4 * A16_B;      // 20480
constexpr int B_RING = 4 * B_STG;        // 40960
constexpr int A16_OFF = A32_RING;        // 32768
constexpr int B_OFF = A32_RING + A16_RING; // 53248
constexpr int K_ITERS = N_SZ / 32;       // 64
constexpr unsigned DYN_B = A32_RING + A16_RING + B_RING + 256;  // 94464

// h kernel tiling (tf32 path)
constexpr int HS = 36;
constexpr int HSTG = 2 * 128 * HS;
constexpr unsigned DYN_H = 2 * HSTG * 4; // 73728 (also covers 128x136 half transpose buf)
constexpr int SHh = 136;                 // h transpose smem stride (halves)

// scratch: hT[b][e][j] = fp16(leaky_relu(x @ W^T))^T
__device__ __half g_hT[(size_t)B_SZ * D_SZ * N_SZ];

// ===================== helpers =====================
__device__ __forceinline__ uint32_t s2u(const void* p) {
    uint32_t a;
    asm("{ .reg .u64 t; cvta.to.shared.u64 t, %1; cvt.u32.u64 %0, t; }" : "=r"(a) : "l"(p));
    return a;
}
__device__ __forceinline__ void cp16(uint32_t dst, const void* src) {
    asm volatile("cp.async.cg.shared.global [%0], [%1], 16;" :: "r"(dst), "l"(src));
}
__device__ __forceinline__ uint32_t f2tf(float f) {
    uint32_t u;
    asm("cvt.rna.tf32.f32 %0, %1;" : "=r"(u) : "f"(f));
    return u;
}
__device__ __forceinline__ void mma_tf32(float* d, const uint32_t* a, const uint32_t* b) {
    asm volatile(
        "mma.sync.aligned.m16n8k8.row.col.f32.tf32.tf32.f32 "
        "{%0,%1,%2,%3}, {%4,%5,%6,%7}, {%8,%9}, {%0,%1,%2,%3};"
        : "+f"(d[0]), "+f"(d[1]), "+f"(d[2]), "+f"(d[3])
        : "r"(a[0]), "r"(a[1]), "r"(a[2]), "r"(a[3]), "r"(b[0]), "r"(b[1]));
}
__device__ __forceinline__ void mma_f16(float* d, const uint32_t* a,
                                        uint32_t b0, uint32_t b1) {
    asm volatile(
        "mma.sync.aligned.m16n8k16.row.col.f32.f16.f16.f32 "
        "{%0,%1,%2,%3}, {%4,%5,%6,%7}, {%8,%9}, {%0,%1,%2,%3};"
        : "+f"(d[0]), "+f"(d[1]), "+f"(d[2]), "+f"(d[3])
        : "r"(a[0]), "r"(a[1]), "r"(a[2]), "r"(a[3]), "r"(b0), "r"(b1));
}
#define LDSM4(r, addr)                                                          \
    asm volatile("ldmatrix.sync.aligned.m8n8.x4.shared.b16 {%0,%1,%2,%3}, [%4];" \
        : "=r"((r)[0]), "=r"((r)[1]), "=r"((r)[2]), "=r"((r)[3]) : "r"(addr))
__device__ __forceinline__ __half lrelu_h(float x) {
    float v = x > 0.f ? x : 0.01f * x;
    return __float2half_rn(v);
}

// ===================== kernel 1: hT = fp16(leaky_relu(x @ W^T))^T ===========
__global__ __launch_bounds__(256) void h_kernel(const float* __restrict__ x,
                                                const float* __restrict__ W) {
    extern __shared__ float hdyn[];
    const int tid = threadIdx.x;
    const int b = blockIdx.x >> 4;
    const int j0 = (blockIdx.x & 15) * 128;

    const int wid = tid >> 5;
    const int lane = tid & 31;
    const int g = lane >> 2;
    const int t4 = lane & 3;
    const int wm = wid & 3;
    const int wn = wid >> 2;

    const uint32_t smem_u = s2u(hdyn);
    const float* xg = x + ((size_t)b * N_SZ + j0) * D_SZ;

    auto load_stage = [&](int stage, int kt) {
        const uint32_t xbase = smem_u + stage * HSTG * 4;
        const uint32_t wbase = xbase + 128 * HS * 4;
#pragma unroll
        for (int i = 0; i < 4; i++) {
            int c = tid + i * 256;
            int r = c >> 3, d4 = (c & 7) * 4;
            cp16(xbase + (r * HS + d4) * 4, xg + (size_t)r * D_SZ + kt * 32 + d4);
            cp16(wbase + (r * HS + d4) * 4, W + (size_t)r * D_SZ + kt * 32 + d4);
        }
    };

    float acc[2][8][4];
#pragma unroll
    for (int mt = 0; mt < 2; mt++)
#pragma unroll
        for (int nt = 0; nt < 8; nt++)
#pragma unroll
            for (int q = 0; q < 4; q++) acc[mt][nt][q] = 0.f;

    load_stage(0, 0);
    asm volatile("cp.async.commit_group;" ::: "memory");

    for (int kt = 0; kt < 4; kt++) {
        asm volatile("cp.async.wait_group 0;" ::: "memory");
        __syncthreads();
        if (kt + 1 < 4) {
            load_stage((kt + 1) & 1, kt + 1);
            asm volatile("cp.async.commit_group;" ::: "memory");
        }
        const float* xs = hdyn + (kt & 1) * HSTG;
        const float* ws = xs + 128 * HS;

#pragma unroll
        for (int ks = 0; ks < 4; ks++) {
            uint32_t af[2][4], bf[8][2];
#pragma unroll
            for (int mt = 0; mt < 2; mt++) {
                int r0 = wm * 32 + mt * 16 + g;
                af[mt][0] = f2tf(xs[r0 * HS + ks * 8 + t4]);
                af[mt][1] = f2tf(xs[(r0 + 8) * HS + ks * 8 + t4]);
                af[mt][2] = f2tf(xs[r0 * HS + ks * 8 + t4 + 4]);
                af[mt][3] = f2tf(xs[(r0 + 8) * HS + ks * 8 + t4 + 4]);
            }
#pragma unroll
            for (int nt = 0; nt < 8; nt++) {
                int c0 = wn * 64 + nt * 8 + g;
                bf[nt][0] = f2tf(ws[c0 * HS + ks * 8 + t4]);
                bf[nt][1] = f2tf(ws[c0 * HS + ks * 8 + t4 + 4]);
            }
#pragma unroll
            for (int mt = 0; mt < 2; mt++)
#pragma unroll
                for (int nt = 0; nt < 8; nt++)
                    mma_tf32(acc[mt][nt], af[mt], bf[nt]);
        }
        __syncthreads();
    }

    // ---- transpose through smem, store fp16 hT[e][j] coalesced ----
    __half* hsm = reinterpret_cast<__half*>(hdyn);
#pragma unroll
    for (int mt = 0; mt < 2; mt++)
#pragma unroll
        for (int nt = 0; nt < 8; nt++) {
            int r = wm * 32 + mt * 16 + g;
            int c = wn * 64 + nt * 8 + t4 * 2;
            hsm[c * SHh + r]           = lrelu_h(acc[mt][nt][0]);
            hsm[(c + 1) * SHh + r]     = lrelu_h(acc[mt][nt][1]);
            hsm[c * SHh + r + 8]       = lrelu_h(acc[mt][nt][2]);
            hsm[(c + 1) * SHh + r + 8] = lrelu_h(acc[mt][nt][3]);
        }
    __syncthreads();

    const int e = tid >> 1;
    const int jh = (tid & 1) * 64;
    uint4* dst = reinterpret_cast<uint4*>(g_hT + ((size_t)b * D_SZ + e) * N_SZ + j0 + jh);
    const uint4* src = reinterpret_cast<const uint4*>(hsm + e * SHh + jh);
#pragma unroll
    for (int q = 0; q < 8; q++) dst[q] = src[q];
}

// ===================== kernel 2: fused normalize + An @ h (fp16 MMA) ========
// out[b,i,e] = ( sum_j A[b,i,j] h[b,j,e] + (1 - A[b,i,i]) h[b,i,e] ) / d_i
// d_i = rowsum(A[b,i,:]) - A[b,i,i] + 1
// CTA 64x128 (R10 chassis), 8 warps of 32x32, ldmatrix fragments (R11-proven)
__global__ __launch_bounds__(256, 2) void gcn_gemm_kernel(const float* __restrict__ A,
                                                          const __half* __restrict__ hTg,
                                                          float* __restrict__ out) {
    extern __shared__ float dyn[];
    __shared__ float rs_sm[512];
    __shared__ float corr_sm[64];
    __shared__ float dinv_sm[64];

    const int tid = threadIdx.x;
    const int b = blockIdx.x >> 5;
    const int gi0 = (blockIdx.x & 31) * 64;

    const int wid = tid >> 5;
    const int lane = tid & 31;
    const int g = lane >> 2;
    const int tg = lane & 3;
    const int wm = wid & 1;      // 2 row slices of 32
    const int wn = wid >> 1;     // 4 col slices of 32

    const float* Ag = A + (size_t)b * N_SZ * N_SZ;
    const __half* hTb = hTg + (size_t)b * D_SZ * N_SZ;

    // align dynamic smem base to 128B
    const uint32_t raw = s2u(dyn);
    const uint32_t base_u = (raw + 127u) & ~127u;
    char* dbase = reinterpret_cast<char*>(dyn) + (base_u - raw);

    const int r_lo = tid >> 3;           // 0..31 (also handles r_lo+32)
    const int kc = (tid & 7) * 4;        // k offset within 32
    float rs0 = 0.f, rs1 = 0.f;

    // ldmatrix per-lane base addresses (bytes, stride 80 = 40 halves)
    // A 16x16 tile (x4): lanes 0-15 rows, k bytes 0-15; lanes 16-31 rows, +16B
    const uint32_t aoff0 = (uint32_t)((wm * 32 + (lane & 15)) * 80 + ((lane >> 4) * 16));
    const uint32_t aoff1 = aoff0 + 16 * 80;
    // B 16-col tile pair: lanes (0-7,8-15) n0-7 k0-7/k8-15; (16-23,24-31) n8-15
    const uint32_t boff0 = (uint32_t)((wn * 32 + (lane & 7) + ((lane >> 4) * 8)) * 80 +
                                      (((lane >> 3) & 1) * 16));
    const uint32_t boff1 = boff0 + 16 * 80;
    const uint32_t aAddr0 = base_u + A16_OFF + aoff0;
    const uint32_t aAddr1 = base_u + A16_OFF + aoff1;
    const uint32_t bAddr0 = base_u + B_OFF + boff0;
    const uint32_t bAddr1 = base_u + B_OFF + boff1;

    // A fp32 tile t -> ring stage t&3 via cp.async (2 cp16/thread, 64 rows)
    auto cpA = [&](int t) {
        const uint32_t ab = base_u + (t & 3) * A32_B;
        const float* p = Ag + (size_t)(gi0 + r_lo) * N_SZ + t * 32 + kc;
        cp16(ab + (r_lo * 32 + kc) * 4, p);
        cp16(ab + ((r_lo + 32) * 32 + kc) * 4, p + (size_t)32 * N_SZ);
    };
    // B tile t -> ring stage t&3 via cp.async
    auto cpB = [&](int t) {
        const uint32_t bbase = base_u + B_OFF + (t & 3) * B_STG;
#pragma unroll
        for (int i = 0; i < 2; i++) {
            int c2 = tid + i * 256;
            int e = c2 >> 2, ch = c2 & 3;
            cp16(bbase + e * (SBH * 2) + ch * 16,
                 hTb + (size_t)e * N_SZ + t * 32 + ch * 8);
        }
    };
    // convert A32 tile t -> A16 stage t&3 (+ rowsum; each element counted once)
    auto convert = [&](int t) {
        const float* a32 = reinterpret_cast<const float*>(dbase + (t & 3) * A32_B);
        float4 v0 = *reinterpret_cast<const float4*>(a32 + r_lo * 32 + kc);
        float4 v1 = *reinterpret_cast<const float4*>(a32 + (r_lo + 32) * 32 + kc);
        __half2* ah = reinterpret_cast<__half2*>(dbase + A16_OFF + (t & 3) * A16_B);
        int i0 = r_lo * (SAH / 2) + (kc >> 1);
        ah[i0]     = __floats2half2_rn(v0.x, v0.y);
        ah[i0 + 1] = __floats2half2_rn(v0.z, v0.w);
        int i1 = (r_lo + 32) * (SAH / 2) + (kc >> 1);
        ah[i1]     = __floats2half2_rn(v1.x, v1.y);
        ah[i1 + 1] = __floats2half2_rn(v1.z, v1.w);
        rs0 += (v0.x + v0.y) + (v0.z + v0.w);
        rs1 += (v1.x + v1.y) + (v1.z + v1.w);
    };

    float acc[2][4][4];
#pragma unroll
    for (int mt = 0; mt < 2; mt++)
#pragma unroll
        for (int nt = 0; nt < 4; nt++)
#pragma unroll
            for (int q = 0; q < 4; q++) acc[mt][nt][q] = 0.f;

    // ---- prologue (race-free; R10-proven) ----
    // g0{A0,A1,A2}, g1{B0,A3}, g2{B1}, [wait g0, convert 0,1], g3{B2,A4}
    cpA(0); cpA(1); cpA(2);
    asm volatile("cp.async.commit_group;" ::: "memory");   // g0
    cpB(0); cpA(3);
    asm volatile("cp.async.commit_group;" ::: "memory");   // g1
    cpB(1);
    asm volatile("cp.async.commit_group;" ::: "memory");   // g2
    asm volatile("cp.async.wait_group 2;" ::: "memory");   // g0 done
    __syncthreads();
    convert(0);
    convert(1);
    cpB(2); cpA(4);                                        // slot 0 write AFTER convert(0)
    asm volatile("cp.async.commit_group;" ::: "memory");   // g3

    // steady state: wait guarantees g(kt+1) = {B(kt), A32(kt+2)}
#pragma unroll 2
    for (int kt = 0; kt < K_ITERS; kt++) {
        asm volatile("cp.async.wait_group 2;" ::: "memory");
        __syncthreads();

        if (kt + 3 < K_ITERS) cpB(kt + 3);
        if (kt + 5 < K_ITERS) cpA(kt + 5);
        asm volatile("cp.async.commit_group;" ::: "memory");

        if (kt + 2 < K_ITERS) convert(kt + 2);

        const uint32_t sA = (kt & 3) * A16_B;
        const uint32_t sB = (kt & 3) * B_STG;

#pragma unroll
        for (int ks = 0; ks < 2; ks++) {
            uint32_t a0[4], a1[4], bf[4], cf[4];
            LDSM4(a0, aAddr0 + sA + ks * 32);
            LDSM4(a1, aAddr1 + sA + ks * 32);
            LDSM4(bf, bAddr0 + sB + ks * 32);
            LDSM4(cf, bAddr1 + sB + ks * 32);
            mma_f16(acc[0][0], a0, bf[0], bf[1]);
            mma_f16(acc[0][1], a0, bf[2], bf[3]);
            mma_f16(acc[0][2], a0, cf[0], cf[1]);
            mma_f16(acc[0][3], a0, cf[2], cf[3]);
            mma_f16(acc[1][0], a1, bf[0], bf[1]);
            mma_f16(acc[1][1], a1, bf[2], bf[3]);
            mma_f16(acc[1][2], a1, cf[0], cf[1]);
            mma_f16(acc[1][3], a1, cf[2], cf[3]);
        }
    }

    // ---- reductions & epilogue ----
    rs_sm[tid] = rs0;
    rs_sm[256 + tid] = rs1;
    __syncthreads();                    // all compute done, rings dead

    if (tid < 64) {
        const float* srcp = (tid < 32) ? (rs_sm + tid * 8) : (rs_sm + 256 + (tid - 32) * 8);
        float d = ((srcp[0] + srcp[1]) + (srcp[2] + srcp[3])) +
                  ((srcp[4] + srcp[5]) + (srcp[6] + srcp[7]));
        float aii = Ag[(size_t)(gi0 + tid) * (N_SZ + 1)];
        float c = 1.0f - aii;           // mask true: A>=0, rows strictly positive
        corr_sm[tid] = c;
        dinv_sm[tid] = 1.0f / (d + c);
    }

    float* o_sm = reinterpret_cast<float*>(dbase);            // [64][132] f32
    float* hf = reinterpret_cast<float*>(dbase) + 64 * 132;   // [128][65] f32
#pragma unroll
    for (int mt = 0; mt < 2; mt++)
#pragma unroll
        for (int nt = 0; nt < 4; nt++) {
            int r = wm * 32 + mt * 16 + g;
            int c = wn * 32 + nt * 8 + tg * 2;
            o_sm[r * 132 + c]           = acc[mt][nt][0];
            o_sm[r * 132 + c + 1]       = acc[mt][nt][1];
            o_sm[(r + 8) * 132 + c]     = acc[mt][nt][2];
            o_sm[(r + 8) * 132 + c + 1] = acc[mt][nt][3];
        }

    // load hT[:, gi0..gi0+64) tile -> float smem (for diag correction)
    {
        const int e = tid >> 1;
        const int part = tid & 1;
        const uint4* src = reinterpret_cast<const uint4*>(
            hTb + (size_t)e * N_SZ + gi0 + part * 32);
#pragma unroll
        for (int q = 0; q < 4; q++) {
            uint4 v = src[q];
            uint32_t w[4] = {v.x, v.y, v.z, v.w};
#pragma unroll
            for (int u = 0; u < 4; u++) {
                float2 f = __half22float2(*reinterpret_cast<__half2*>(&w[u]));
                hf[e * 65 + part * 32 + q * 8 + u * 2]     = f.x;
                hf[e * 65 + part * 32 + q * 8 + u * 2 + 1] = f.y;
            }
        }
    }
    __syncthreads();

    float* ob = out + ((size_t)b * N_SZ + gi0) * D_SZ;
#pragma unroll 8
    for (int i = tid; i < 64 * 128; i += 256) {
        int r = i >> 7, e = i & 127;
        ob[i] = (o_sm[r * 132 + e] + corr_sm[r] * hf[e * 65 + r]) * dinv_sm[r];
    }
}

// ===================== host =====================
extern "C" void kernel_launch(void* const* d_in, const int* in_sizes, int n_in,
                              void* d_out, int out_size) {
    const float* x = (const float*)d_in[0];
    const float* A = (const float*)d_in[1];
    const float* W = (const float*)d_in[2];
    float* out = (float*)d_out;

    void* hT_ptr = nullptr;
    cudaGetSymbolAddress(&hT_ptr, g_hT);

    cudaFuncSetAttribute(h_kernel, cudaFuncAttributeMaxDynamicSharedMemorySize, DYN_H);
    h_kernel<<<B_SZ * (N_SZ / 128), 256, DYN_H>>>(x, W);

    cudaFuncSetAttribute(gcn_gemm_kernel, cudaFuncAttributeMaxDynamicSharedMemorySize, DYN_B);
    gcn_gemm_kernel<<<B_SZ * (N_SZ / 64), 256, DYN_B>>>(A, (const __half*)hT_ptr, out);
    (void)in_sizes; (void)n_in; (void)out_size;
}

// round 13
// speedup vs baseline: 1.3456x; 1.0319x over previous
#include <cuda_runtime.h>
#include <cuda_fp16.h>
#include <cstdint>
#include <cstddef>

// ===================== problem constants =====================
constexpr int B_SZ = 8;
constexpr int N_SZ = 2048;
constexpr int D_SZ = 128;

// ============ GEMM tiling: CTA 64(M) x 128(N) x 64(K), K_IT=32 ============
constexpr int K_IT = 32;
constexpr int A16_STG = 64 * 144;        // 9216 B (64 rows x 72 halves)
constexpr int B_STG = 128 * 144;         // 18432 B (128 rows x 72 halves)
constexpr int B_OFF = 2 * A16_STG;       // A16 ring-2 then B ring-3
constexpr unsigned DYN_B = B_OFF + 3 * B_STG + 256;  // 73984

// h kernel tiling (tf32 path)
constexpr int HS = 36;
constexpr int HSTG = 2 * 128 * HS;
constexpr unsigned DYN_H = 2 * HSTG * 4; // 73728 (also covers 128x136 half transpose buf)
constexpr int SHh = 136;                 // h transpose smem stride (halves)

// scratch: hT[b][e][j] = fp16(leaky_relu(x @ W^T))^T
__device__ __half g_hT[(size_t)B_SZ * D_SZ * N_SZ];

// ===================== helpers =====================
__device__ __forceinline__ uint32_t s2u(const void* p) {
    uint32_t a;
    asm("{ .reg .u64 t; cvta.to.shared.u64 t, %1; cvt.u32.u64 %0, t; }" : "=r"(a) : "l"(p));
    return a;
}
__device__ __forceinline__ void cp16(uint32_t dst, const void* src) {
    asm volatile("cp.async.cg.shared.global [%0], [%1], 16;" :: "r"(dst), "l"(src));
}
__device__ __forceinline__ uint32_t f2tf(float f) {
    uint32_t u;
    asm("cvt.rna.tf32.f32 %0, %1;" : "=r"(u) : "f"(f));
    return u;
}
__device__ __forceinline__ void mma_tf32(float* d, const uint32_t* a, const uint32_t* b) {
    asm volatile(
        "mma.sync.aligned.m16n8k8.row.col.f32.tf32.tf32.f32 "
        "{%0,%1,%2,%3}, {%4,%5,%6,%7}, {%8,%9}, {%0,%1,%2,%3};"
        : "+f"(d[0]), "+f"(d[1]), "+f"(d[2]), "+f"(d[3])
        : "r"(a[0]), "r"(a[1]), "r"(a[2]), "r"(a[3]), "r"(b[0]), "r"(b[1]));
}
__device__ __forceinline__ void mma_f16(float* d, const uint32_t* a,
                                        uint32_t b0, uint32_t b1) {
    asm volatile(
        "mma.sync.aligned.m16n8k16.row.col.f32.f16.f16.f32 "
        "{%0,%1,%2,%3}, {%4,%5,%6,%7}, {%8,%9}, {%0,%1,%2,%3};"
        : "+f"(d[0]), "+f"(d[1]), "+f"(d[2]), "+f"(d[3])
        : "r"(a[0]), "r"(a[1]), "r"(a[2]), "r"(a[3]), "r"(b0), "r"(b1));
}
#define LDSM4(r, addr)                                                          \
    asm volatile("ldmatrix.sync.aligned.m8n8.x4.shared.b16 {%0,%1,%2,%3}, [%4];" \
        : "=r"((r)[0]), "=r"((r)[1]), "=r"((r)[2]), "=r"((r)[3]) : "r"(addr))
__device__ __forceinline__ __half lrelu_h(float x) {
    float v = x > 0.f ? x : 0.01f * x;
    return __float2half_rn(v);
}
__device__ __forceinline__ uint32_t h2u(__half2 h) {
    return *reinterpret_cast<uint32_t*>(&h);
}

// ===================== kernel 1: hT = fp16(leaky_relu(x @ W^T))^T ===========
__global__ __launch_bounds__(256) void h_kernel(const float* __restrict__ x,
                                                const float* __restrict__ W) {
    extern __shared__ float hdyn[];
    const int tid = threadIdx.x;
    const int b = blockIdx.x >> 4;
    const int j0 = (blockIdx.x & 15) * 128;

    const int wid = tid >> 5;
    const int lane = tid & 31;
    const int g = lane >> 2;
    const int t4 = lane & 3;
    const int wm = wid & 3;
    const int wn = wid >> 2;

    const uint32_t smem_u = s2u(hdyn);
    const float* xg = x + ((size_t)b * N_SZ + j0) * D_SZ;

    auto load_stage = [&](int stage, int kt) {
        const uint32_t xbase = smem_u + stage * HSTG * 4;
        const uint32_t wbase = xbase + 128 * HS * 4;
#pragma unroll
        for (int i = 0; i < 4; i++) {
            int c = tid + i * 256;
            int r = c >> 3, d4 = (c & 7) * 4;
            cp16(xbase + (r * HS + d4) * 4, xg + (size_t)r * D_SZ + kt * 32 + d4);
            cp16(wbase + (r * HS + d4) * 4, W + (size_t)r * D_SZ + kt * 32 + d4);
        }
    };

    float acc[2][8][4];
#pragma unroll
    for (int mt = 0; mt < 2; mt++)
#pragma unroll
        for (int nt = 0; nt < 8; nt++)
#pragma unroll
            for (int q = 0; q < 4; q++) acc[mt][nt][q] = 0.f;

    load_stage(0, 0);
    asm volatile("cp.async.commit_group;" ::: "memory");

    for (int kt = 0; kt < 4; kt++) {
        asm volatile("cp.async.wait_group 0;" ::: "memory");
        __syncthreads();
        if (kt + 1 < 4) {
            load_stage((kt + 1) & 1, kt + 1);
            asm volatile("cp.async.commit_group;" ::: "memory");
        }
        const float* xs = hdyn + (kt & 1) * HSTG;
        const float* ws = xs + 128 * HS;

#pragma unroll
        for (int ks = 0; ks < 4; ks++) {
            uint32_t af[2][4], bf[8][2];
#pragma unroll
            for (int mt = 0; mt < 2; mt++) {
                int r0 = wm * 32 + mt * 16 + g;
                af[mt][0] = f2tf(xs[r0 * HS + ks * 8 + t4]);
                af[mt][1] = f2tf(xs[(r0 + 8) * HS + ks * 8 + t4]);
                af[mt][2] = f2tf(xs[r0 * HS + ks * 8 + t4 + 4]);
                af[mt][3] = f2tf(xs[(r0 + 8) * HS + ks * 8 + t4 + 4]);
            }
#pragma unroll
            for (int nt = 0; nt < 8; nt++) {
                int c0 = wn * 64 + nt * 8 + g;
                bf[nt][0] = f2tf(ws[c0 * HS + ks * 8 + t4]);
                bf[nt][1] = f2tf(ws[c0 * HS + ks * 8 + t4 + 4]);
            }
#pragma unroll
            for (int mt = 0; mt < 2; mt++)
#pragma unroll
                for (int nt = 0; nt < 8; nt++)
                    mma_tf32(acc[mt][nt], af[mt], bf[nt]);
        }
        __syncthreads();
    }

    // ---- transpose through smem, store fp16 hT[e][j] coalesced ----
    __half* hsm = reinterpret_cast<__half*>(hdyn);
#pragma unroll
    for (int mt = 0; mt < 2; mt++)
#pragma unroll
        for (int nt = 0; nt < 8; nt++) {
            int r = wm * 32 + mt * 16 + g;
            int c = wn * 64 + nt * 8 + t4 * 2;
            hsm[c * SHh + r]           = lrelu_h(acc[mt][nt][0]);
            hsm[(c + 1) * SHh + r]     = lrelu_h(acc[mt][nt][1]);
            hsm[c * SHh + r + 8]       = lrelu_h(acc[mt][nt][2]);
            hsm[(c + 1) * SHh + r + 8] = lrelu_h(acc[mt][nt][3]);
        }
    __syncthreads();

    const int e = tid >> 1;
    const int jh = (tid & 1) * 64;
    uint4* dst = reinterpret_cast<uint4*>(g_hT + ((size_t)b * D_SZ + e) * N_SZ + j0 + jh);
    const uint4* src = reinterpret_cast<const uint4*>(hsm + e * SHh + jh);
#pragma unroll
    for (int q = 0; q < 8; q++) dst[q] = src[q];
}

// ===================== kernel 2: fused normalize + An @ h (fp16 MMA) ========
// out[b,i,e] = ( sum_j A[b,i,j] h[b,j,e] + (1 - A[b,i,i]) h[b,i,e] ) / d_i
// d_i = rowsum(A[b,i,:]) - A[b,i,i] + 1
// BK=64: A via LDG->regs (1-iter cover) -> STS fp16 ring-2; B cp.async ring-3
__global__ __launch_bounds__(256, 2) void gcn_gemm_kernel(const float* __restrict__ A,
                                                          const __half* __restrict__ hTg,
                                                          float* __restrict__ out) {
    extern __shared__ float dyn[];
    __shared__ float rs_sm[256];
    __shared__ float corr_sm[64];
    __shared__ float dinv_sm[64];

    const int tid = threadIdx.x;
    const int b = blockIdx.x >> 5;
    const int gi0 = (blockIdx.x & 31) * 64;

    const int wid = tid >> 5;
    const int lane = tid & 31;
    const int g = lane >> 2;
    const int tg = lane & 3;
    const int wm = wid & 1;      // 2 row slices of 32
    const int wn = wid >> 1;     // 4 col slices of 32

    const float* Ag = A + (size_t)b * N_SZ * N_SZ;
    const __half* hTb = hTg + (size_t)b * D_SZ * N_SZ;

    const uint32_t raw = s2u(dyn);
    const uint32_t base_u = (raw + 127u) & ~127u;
    char* dbase = reinterpret_cast<char*>(dyn) + (base_u - raw);

    // A path thread mapping: 4 threads/row, 16 consecutive floats each
    const int arow = tid >> 2;           // 0..63
    const int aq = tid & 3;              // quarter (16 floats)
    float rs = 0.f;

    // ldmatrix lane addresses (row stride 144 B = 72 halves, conflict-free)
    const uint32_t aAddr0 = base_u + (uint32_t)((wm * 32 + (lane & 15)) * 144 +
                                                ((lane >> 4) * 16));
    const uint32_t aAddr1 = aAddr0 + 16 * 144;
    const uint32_t bAddr0 = base_u + B_OFF +
        (uint32_t)((wn * 32 + (lane & 7) + ((lane >> 4) * 8)) * 144 +
                   (((lane >> 3) & 1) * 16));
    const uint32_t bAddr1 = bAddr0 + 16 * 144;

    float4 rv0, rv1, rv2, rv3;           // staged A tile (16 floats/thread)

    auto ldgA = [&](int t) {
        const float* p = Ag + (size_t)(gi0 + arow) * N_SZ + t * 64 + aq * 16;
        rv0 = *reinterpret_cast<const float4*>(p);
        rv1 = *reinterpret_cast<const float4*>(p + 4);
        rv2 = *reinterpret_cast<const float4*>(p + 8);
        rv3 = *reinterpret_cast<const float4*>(p + 12);
    };
    // STS fp16 (2x STS.128) + rowsum from the fp32 staged regs (counted once)
    auto stsA = [&](int slot) {
        uint4 u0, u1;
        u0.x = h2u(__floats2half2_rn(rv0.x, rv0.y));
        u0.y = h2u(__floats2half2_rn(rv0.z, rv0.w));
        u0.z = h2u(__floats2half2_rn(rv1.x, rv1.y));
        u0.w = h2u(__floats2half2_rn(rv1.z, rv1.w));
        u1.x = h2u(__floats2half2_rn(rv2.x, rv2.y));
        u1.y = h2u(__floats2half2_rn(rv2.z, rv2.w));
        u1.z = h2u(__floats2half2_rn(rv3.x, rv3.y));
        u1.w = h2u(__floats2half2_rn(rv3.z, rv3.w));
        uint4* p = reinterpret_cast<uint4*>(dbase + slot * A16_STG + arow * 144 + aq * 32);
        p[0] = u0;
        p[1] = u1;
        rs += ((rv0.x + rv0.y) + (rv0.z + rv0.w)) + ((rv1.x + rv1.y) + (rv1.z + rv1.w)) +
              ((rv2.x + rv2.y) + (rv2.z + rv2.w)) + ((rv3.x + rv3.y) + (rv3.z + rv3.w));
    };
    // B tile t -> given ring slot (128 e-rows x 64 halves, 4 cp16/thread)
    auto cpB = [&](int t, int slot) {
        const uint32_t bb = base_u + B_OFF + slot * B_STG;
#pragma unroll
        for (int i = 0; i < 4; i++) {
            int c2 = tid + i * 256;
            int e = c2 >> 3, ch = c2 & 7;
            cp16(bb + e * 144 + ch * 16,
                 hTb + (size_t)e * N_SZ + t * 64 + ch * 8);
        }
    };

    float acc[2][4][4];
#pragma unroll
    for (int mt = 0; mt < 2; mt++)
#pragma unroll
        for (int nt = 0; nt < 4; nt++)
#pragma unroll
            for (int q = 0; q < 4; q++) acc[mt][nt][q] = 0.f;

    // ---- prologue ----
    ldgA(0);
    cpB(0, 0);
    asm volatile("cp.async.commit_group;" ::: "memory");   // g0 = B0
    cpB(1, 1);
    asm volatile("cp.async.commit_group;" ::: "memory");   // g1 = B1
    stsA(0);                                               // tile0 -> A16 slot0 (one-time stall)
    ldgA(1);

    int sBr = 0, sBw = 2;
    for (int kt = 0; kt < K_IT; kt++) {
        asm volatile("cp.async.wait_group 1;" ::: "memory");  // B(kt) resident (per-thread)
        __syncthreads();                                       // all waits done; old slots dead

        if (kt + 2 < K_IT) cpB(kt + 2, sBw);                   // slot of B(kt-1): dead
        asm volatile("cp.async.commit_group;" ::: "memory");
        if (kt < K_IT - 1) stsA((kt + 1) & 1);                 // tile kt+1 from staged regs
        if (kt + 2 < K_IT) ldgA(kt + 2);                       // refill regs (1-iter cover)

        const uint32_t offA = (uint32_t)(kt & 1) * A16_STG;
        const uint32_t offB = (uint32_t)sBr * B_STG;

#pragma unroll
        for (int ks = 0; ks < 4; ks++) {
            uint32_t a0[4], a1[4], bf[4], cf[4];
            LDSM4(a0, aAddr0 + offA + ks * 32);
            LDSM4(a1, aAddr1 + offA + ks * 32);
            LDSM4(bf, bAddr0 + offB + ks * 32);
            LDSM4(cf, bAddr1 + offB + ks * 32);
            mma_f16(acc[0][0], a0, bf[0], bf[1]);
            mma_f16(acc[0][1], a0, bf[2], bf[3]);
            mma_f16(acc[0][2], a0, cf[0], cf[1]);
            mma_f16(acc[0][3], a0, cf[2], cf[3]);
            mma_f16(acc[1][0], a1, bf[0], bf[1]);
            mma_f16(acc[1][1], a1, bf[2], bf[3]);
            mma_f16(acc[1][2], a1, cf[0], cf[1]);
            mma_f16(acc[1][3], a1, cf[2], cf[3]);
        }
        sBr = (sBr == 2) ? 0 : sBr + 1;
        sBw = (sBw == 2) ? 0 : sBw + 1;
    }

    // ---- reductions & epilogue ----
    rs_sm[tid] = rs;
    __syncthreads();                    // all compute done, rings dead

    if (tid < 64) {
        const float* srcp = rs_sm + tid * 4;
        float d = (srcp[0] + srcp[1]) + (srcp[2] + srcp[3]);
        float aii = Ag[(size_t)(gi0 + tid) * (N_SZ + 1)];
        float c = 1.0f - aii;           // mask true: A>=0, rows strictly positive
        corr_sm[tid] = c;
        dinv_sm[tid] = 1.0f / (d + c);
    }

    float* o_sm = reinterpret_cast<float*>(dbase);            // [64][132] f32 (33792 B)
    float* hf = reinterpret_cast<float*>(dbase) + 64 * 132;   // [128][65] f32 (33280 B)
#pragma unroll
    for (int mt = 0; mt < 2; mt++)
#pragma unroll
        for (int nt = 0; nt < 4; nt++) {
            int r = wm * 32 + mt * 16 + g;
            int c = wn * 32 + nt * 8 + tg * 2;
            o_sm[r * 132 + c]           = acc[mt][nt][0];
            o_sm[r * 132 + c + 1]       = acc[mt][nt][1];
            o_sm[(r + 8) * 132 + c]     = acc[mt][nt][2];
            o_sm[(r + 8) * 132 + c + 1] = acc[mt][nt][3];
        }

    // load hT[:, gi0..gi0+64) tile -> float smem (for diag correction)
    {
        const int e = tid >> 1;
        const int part = tid & 1;
        const uint4* src = reinterpret_cast<const uint4*>(
            hTb + (size_t)e * N_SZ + gi0 + part * 32);
#pragma unroll
        for (int q = 0; q < 4; q++) {
            uint4 v = src[q];
            uint32_t w[4] = {v.x, v.y, v.z, v.w};
#pragma unroll
            for (int u = 0; u < 4; u++) {
                float2 f = __half22float2(*reinterpret_cast<__half2*>(&w[u]));
                hf[e * 65 + part * 32 + q * 8 + u * 2]     = f.x;
                hf[e * 65 + part * 32 + q * 8 + u * 2 + 1] = f.y;
            }
        }
    }
    __syncthreads();

    float* ob = out + ((size_t)b * N_SZ + gi0) * D_SZ;
#pragma unroll 8
    for (int i = tid; i < 64 * 128; i += 256) {
        int r = i >> 7, e = i & 127;
        ob[i] = (o_sm[r * 132 + e] + corr_sm[r] * hf[e * 65 + r]) * dinv_sm[r];
    }
}

// ===================== host =====================
extern "C" void kernel_launch(void* const* d_in, const int* in_sizes, int n_in,
                              void* d_out, int out_size) {
    const float* x = (const float*)d_in[0];
    const float* A = (const float*)d_in[1];
    const float* W = (const float*)d_in[2];
    float* out = (float*)d_out;

    void* hT_ptr = nullptr;
    cudaGetSymbolAddress(&hT_ptr, g_hT);

    cudaFuncSetAttribute(h_kernel, cudaFuncAttributeMaxDynamicSharedMemorySize, DYN_H);
    h_kernel<<<B_SZ * (N_SZ / 128), 256, DYN_H>>>(x, W);

    cudaFuncSetAttribute(gcn_gemm_kernel, cudaFuncAttributeMaxDynamicSharedMemorySize, DYN_B);
    gcn_gemm_kernel<<<B_SZ * (N_SZ / 64), 256, DYN_B>>>(A, (const __half*)hT_ptr, out);
    (void)in_sizes; (void)n_in; (void)out_size;
}